// round 15
// baseline (speedup 1.0000x reference)
#include <cuda_runtime.h>
#include <cstdint>

// Shapes (fixed): B=4, N=50000
//  f1:[B,64,56,56] f2:[B,128,28,28] f3:[B,256,14,14] f4:[B,512,7,7]
//  out:[B,N,963] = 3 coord + 64 + 128 + 256 + 512

#define BMAX 4
#define NMAX 50048
#define CELLS3 196   // 14*14 f3 cells; f3 cells nest inside f4 cells

// Transposed feature scratch: [b][x][y][c] (channel-contiguous per texel)
__device__ float g_t1[BMAX * 56 * 56 * 64];
__device__ float g_t2[BMAX * 28 * 28 * 128];
__device__ float g_t3[BMAX * 14 * 14 * 256];
__device__ float g_t4[BMAX * 7  * 7  * 512];

// Bucketing state (rebuilt every call; deterministic output regardless of
// atomic ordering because each point writes only its own output row).
__device__ int    g_hist[CELLS3];
__device__ int    g_cursor[CELLS3];
__device__ int    g_sn[NMAX];      // point index, sorted by f3 cell
__device__ float2 g_shw[NMAX];     // (h, w) of that point

// ---------------------------------------------------------------------------
// Fused transpose: all four [B,C,S,S] -> [B,S,S,C] in one launch.
// ---------------------------------------------------------------------------
__device__ __forceinline__ void tr_body(const float* __restrict__ in,
                                        float* __restrict__ out,
                                        int C, int S, int idx) {
    int c = idx % C;
    int y = (idx / C) % S;
    int x = (idx / (C * S)) % S;
    int b = idx / (C * S * S);
    out[idx] = in[((b * C + c) * S + x) * S + y];
}

__global__ __launch_bounds__(256)
void transpose_all(const float* __restrict__ f1, const float* __restrict__ f2,
                   const float* __restrict__ f3, const float* __restrict__ f4,
                   float* __restrict__ t1, float* __restrict__ t2,
                   float* __restrict__ t3, float* __restrict__ t4,
                   int n1, int n2, int n3, int n4) {
    int idx = blockIdx.x * blockDim.x + threadIdx.x;
    if (idx < n1)                     { tr_body(f1, t1, 64, 56, idx); return; }
    idx -= n1;
    if (idx < n2)                     { tr_body(f2, t2, 128, 28, idx); return; }
    idx -= n2;
    if (idx < n3)                     { tr_body(f3, t3, 256, 14, idx); return; }
    idx -= n3;
    if (idx < n4)                     { tr_body(f4, t4, 512, 7, idx); }
}

// ---------------------------------------------------------------------------
// Projection: identical math to the reference.
// ---------------------------------------------------------------------------
__device__ __forceinline__ void proj_hw(const float* __restrict__ coord, int n,
                                        float& h, float& w) {
    float X = coord[3 * n + 0];
    float Y = coord[3 * n + 1];
    float Z = coord[3 * n + 2];
    float negZ = -Z;
    h = fminf(fmaxf(250.0f * (-Y) / negZ + 112.0f, 0.0f), 223.0f);
    w = fminf(fmaxf(250.0f * X / negZ + 112.0f, 0.0f), 223.0f);
}

__device__ __forceinline__ int cell3_of(float h, float w) {
    float x = fminf(h * 0.0625f, 13.0f);
    float y = fminf(w * 0.0625f, 13.0f);
    return (int)floorf(x) * 14 + (int)floorf(y);
}

// ---------------------------------------------------------------------------
// Bucketing pipeline (all tiny).
// ---------------------------------------------------------------------------
__global__ void prep_kernel() {
    int i = threadIdx.x;
    if (i < CELLS3) g_hist[i] = 0;
}

__global__ void count_kernel(const float* __restrict__ coord, int N) {
    int n = blockIdx.x * 256 + threadIdx.x;
    if (n >= N) return;
    float h, w;
    proj_hw(coord, n, h, w);
    atomicAdd(&g_hist[cell3_of(h, w)], 1);
}

__global__ void scan_kernel() {
    if (threadIdx.x == 0 && blockIdx.x == 0) {
        int acc = 0;
        #pragma unroll 4
        for (int i = 0; i < CELLS3; i++) {
            int c = g_hist[i];
            g_cursor[i] = acc;
            acc += c;
        }
    }
}

__global__ void scatter_kernel(const float* __restrict__ coord, int N) {
    int n = blockIdx.x * 256 + threadIdx.x;
    if (n >= N) return;
    float h, w;
    proj_hw(coord, n, h, w);
    int slot = atomicAdd(&g_cursor[cell3_of(h, w)], 1);
    g_sn[slot] = n;
    g_shw[slot] = make_float2(h, w);
}

// ---------------------------------------------------------------------------
// Sorted gather for f3/f4: one warp per 32 sorted points (one cell almost
// always). Fast path: 4 corner rows held in registers, loop points doing only
// FMA + dense streaming stores. Slow path (mixed cells, rare): per-point
// loads, same as the flat kernel.
// Weights use true floor/ceil (exact zeros on integer coords); row indices
// use min(x1+1,S-1) — the clamped row only ever sees weight 0.
// ---------------------------------------------------------------------------
template<int S, int CFULL, int J, bool ZSPLIT>
__global__ __launch_bounds__(128)
void gather_sorted(const float* __restrict__ t, float* __restrict__ out,
                   int N, float invsc, int ch_off_base) {
    const int lane  = threadIdx.x & 31;
    const int wid   = threadIdx.x >> 5;
    const int chunk = blockIdx.x * 4 + wid;
    const int start = chunk * 32;
    if (start >= N) return;
    const int b   = blockIdx.y;
    const int z   = ZSPLIT ? blockIdx.z : 0;
    const int cnt = min(32, N - start);
    const int ch_off = ch_off_base + (ZSPLIT ? 256 * z : 0);

    float4 w = make_float4(0.f, 0.f, 0.f, 0.f);
    int o0 = 0, o1 = 0, o2 = 0, o3 = 0;
    unsigned obase = 0;
    if (lane < cnt) {
        int i = start + lane;
        float2 hw = g_shw[i];
        int n = g_sn[i];
        float x = fminf(hw.x * invsc, (float)(S - 1));
        float y = fminf(hw.y * invsc, (float)(S - 1));
        float x1f = floorf(x), x2f = ceilf(x);
        float y1f = floorf(y), y2f = ceilf(y);
        int x1 = (int)x1f, y1 = (int)y1f;
        int x2 = min(x1 + 1, S - 1), y2 = min(y1 + 1, S - 1);
        float ax2 = x2f - x, ax1 = x - x1f;
        float ay2 = y2f - y, ay1 = y - y1f;
        w = make_float4(ax2 * ay2, ax1 * ay2, ax2 * ay1, ax1 * ay1);
        int base = b * S * S * CFULL + (ZSPLIT ? 256 * z : 0);
        o0 = base + (x1 * S + y1) * CFULL;
        o1 = base + (x2 * S + y1) * CFULL;
        o2 = base + (x1 * S + y2) * CFULL;
        o3 = base + (x2 * S + y2) * CFULL;
        obase = (unsigned)(b * N + n) * 963u + (unsigned)ch_off;
    }
    const unsigned FULL = 0xffffffffu;
    int f0 = __shfl_sync(FULL, o0, 0);
    int f1 = __shfl_sync(FULL, o1, 0);
    int f2 = __shfl_sync(FULL, o2, 0);
    int f3 = __shfl_sync(FULL, o3, 0);
    bool same = (lane < cnt) ? (o0 == f0 && o1 == f1 && o2 == f2 && o3 == f3)
                             : true;
    if (__all_sync(FULL, same)) {
        float r0[J], r1[J], r2[J], r3[J];
        #pragma unroll
        for (int j = 0; j < J; j++) {
            r0[j] = t[f0 + lane + 32 * j];
            r1[j] = t[f1 + lane + 32 * j];
            r2[j] = t[f2 + lane + 32 * j];
            r3[j] = t[f3 + lane + 32 * j];
        }
        for (int p = 0; p < cnt; p++) {
            float wx = __shfl_sync(FULL, w.x, p);
            float wy = __shfl_sync(FULL, w.y, p);
            float wz = __shfl_sync(FULL, w.z, p);
            float ww = __shfl_sync(FULL, w.w, p);
            unsigned ob = __shfl_sync(FULL, obase, p);
            #pragma unroll
            for (int j = 0; j < J; j++)
                __stcs(out + ob + lane + 32 * j,
                       wx * r0[j] + wy * r1[j] + wz * r2[j] + ww * r3[j]);
        }
    } else {
        for (int p = 0; p < cnt; p++) {
            float wx = __shfl_sync(FULL, w.x, p);
            float wy = __shfl_sync(FULL, w.y, p);
            float wz = __shfl_sync(FULL, w.z, p);
            float ww = __shfl_sync(FULL, w.w, p);
            unsigned ob = __shfl_sync(FULL, obase, p);
            int p0 = __shfl_sync(FULL, o0, p);
            int p1 = __shfl_sync(FULL, o1, p);
            int p2 = __shfl_sync(FULL, o2, p);
            int p3 = __shfl_sync(FULL, o3, p);
            #pragma unroll
            for (int j = 0; j < J; j++)
                __stcs(out + ob + lane + 32 * j,
                       wx * t[p0 + lane + 32 * j] + wy * t[p1 + lane + 32 * j]
                     + wz * t[p2 + lane + 32 * j] + ww * t[p3 + lane + 32 * j]);
        }
    }
}

// ---------------------------------------------------------------------------
// Flat gather for f1/f2 (+ coord channels). Same as R13 (proven).
// ---------------------------------------------------------------------------
__device__ __forceinline__ void level_params(float h, float w, float invsc,
                                             int S, int C, int base,
                                             float4* wout, int4* oout) {
    float x = fminf(h * invsc, (float)(S - 1));
    float y = fminf(w * invsc, (float)(S - 1));
    float x1f = floorf(x), x2f = ceilf(x);
    float y1f = floorf(y), y2f = ceilf(y);
    int x1 = (int)x1f, x2 = (int)x2f, y1 = (int)y1f, y2 = (int)y2f;
    float ax2 = x2f - x, ax1 = x - x1f;
    float ay2 = y2f - y, ay1 = y - y1f;
    *oout = make_int4(base + (x1 * S + y1) * C,
                      base + (x2 * S + y1) * C,
                      base + (x1 * S + y2) * C,
                      base + (x2 * S + y2) * C);
    *wout = make_float4(ax2 * ay2, ax1 * ay2, ax2 * ay1, ax1 * ay1);
}

template<int TPP, int PT, int LOG_TPP, bool WRITE_COORD>
__device__ __forceinline__ void gather_body(int tile, int b,
                                            const float* __restrict__ coord,
                                            const float* __restrict__ t,
                                            float* __restrict__ out,
                                            int N, int S, float invsc, int ch_off) {
    __shared__ float4 sw[PT];
    __shared__ int4   so[PT];

    const int n0  = tile * PT;
    const int tid = threadIdx.x;
    constexpr int C = TPP * 4;

    if (tid < PT) {
        int n = n0 + tid;
        if (n < N) {
            float X = coord[3 * n + 0];
            float Y = coord[3 * n + 1];
            float Z = coord[3 * n + 2];
            float negZ = -Z;
            float h = fminf(fmaxf(250.0f * (-Y) / negZ + 112.0f, 0.0f), 223.0f);
            float w = fminf(fmaxf(250.0f * X / negZ + 112.0f, 0.0f), 223.0f);
            level_params(h, w, invsc, S, C, b * S * S * C, &sw[tid], &so[tid]);
            if (WRITE_COORD) {
                float* oc = out + ((unsigned)(b * N + n)) * 963u;
                __stcs(oc + 0, X);
                __stcs(oc + 1, Y);
                __stcs(oc + 2, Z);
            }
        }
    }
    __syncthreads();

    const int p = tid >> LOG_TPP;
    const int q = tid & (TPP - 1);
    const int n = n0 + p;
    if (n >= N) return;

    const float4 w4 = sw[p];
    const int4   o4 = so[p];
    const float* __restrict__ b0 = t + o4.x + q;
    const float* __restrict__ b1 = t + o4.y + q;
    const float* __restrict__ b2 = t + o4.z + q;
    const float* __restrict__ b3 = t + o4.w + q;
    float* o = out + ((unsigned)(b * N + n) * 963u + (unsigned)(ch_off + q));

    float v0[4], v1[4], v2[4], v3[4];
    #pragma unroll
    for (int j = 0; j < 4; j++) {
        v0[j] = b0[TPP * j];
        v1[j] = b1[TPP * j];
        v2[j] = b2[TPP * j];
        v3[j] = b3[TPP * j];
    }
    #pragma unroll
    for (int j = 0; j < 4; j++) {
        __stcs(o + TPP * j, w4.x * v0[j] + w4.y * v1[j] + w4.z * v2[j] + w4.w * v3[j]);
    }
}

__global__ __launch_bounds__(256)
void gather_f1f2(const float* __restrict__ coord,
                 const float* __restrict__ t1, const float* __restrict__ t2,
                 float* __restrict__ out, int N, int e2) {
    const int bid = blockIdx.x;
    const int b   = blockIdx.y;
    if (bid < e2) {
        gather_body<32, 8, 5, false>(bid, b, coord, t2, out, N, 28, 0.125f, 67);
    } else {
        gather_body<16, 16, 4, true>(bid - e2, b, coord, t1, out, N, 56, 0.25f, 3);
    }
}

// ---------------------------------------------------------------------------
extern "C" void kernel_launch(void* const* d_in, const int* in_sizes, int n_in,
                              void* d_out, int out_size) {
    const float* inputs = (const float*)d_in[0];  // [B,N,3]; coord = inputs[0]
    const float* f1 = (const float*)d_in[1];
    const float* f2 = (const float*)d_in[2];
    const float* f3 = (const float*)d_in[3];
    const float* f4 = (const float*)d_in[4];
    float* out = (float*)d_out;

    const int B = in_sizes[1] / (64 * 56 * 56);
    const int N = in_sizes[0] / (3 * B);

    float* t1; float* t2; float* t3; float* t4;
    cudaGetSymbolAddress((void**)&t1, g_t1);
    cudaGetSymbolAddress((void**)&t2, g_t2);
    cudaGetSymbolAddress((void**)&t3, g_t3);
    cudaGetSymbolAddress((void**)&t4, g_t4);

    const int n1 = B * 64 * 56 * 56;
    const int n2 = B * 128 * 28 * 28;
    const int n3 = B * 256 * 14 * 14;
    const int n4 = B * 512 * 7 * 7;
    {
        int total = n1 + n2 + n3 + n4;
        transpose_all<<<(total + 255) / 256, 256>>>(f1, f2, f3, f4,
                                                    t1, t2, t3, t4,
                                                    n1, n2, n3, n4);
    }

    // Bucketing pipeline (sort points by f3 cell; f3 cells nest in f4 cells).
    prep_kernel<<<1, 256>>>();
    count_kernel<<<(N + 255) / 256, 256>>>(inputs, N);
    scan_kernel<<<1, 32>>>();
    scatter_kernel<<<(N + 255) / 256, 256>>>(inputs, N);

    // f3/f4 sorted gathers: 1 warp per 32 sorted points, 4 warps per CTA.
    const int chunks = (N + 31) / 32;
    const int gx = (chunks + 3) / 4;
    {
        dim3 grid(gx, B);
        gather_sorted<14, 256, 8, false><<<grid, 128>>>(t3, out, N, 0.0625f, 195);
    }
    {
        dim3 grid(gx, B, 2);   // z = channel half of f4
        gather_sorted<7, 512, 8, true><<<grid, 128>>>(t4, out, N, 0.03125f, 451);
    }

    // f1/f2 + coord via the flat kernel.
    const int nb2 = (N + 7) / 8;
    const int nb1 = (N + 15) / 16;
    dim3 grid(nb2 + nb1, B);
    gather_f1f2<<<grid, 256>>>(inputs, t1, t2, out, N, nb2);
}

// round 17
// speedup vs baseline: 1.2539x; 1.2539x over previous
#include <cuda_runtime.h>
#include <cstdint>

// Shapes (fixed): B=4, N=50000
//  f1:[B,64,56,56] f2:[B,128,28,28] f3:[B,256,14,14] f4:[B,512,7,7]
//  out:[B,N,963] = 3 coord + 64 + 128 + 256 + 512

#define BMAX 4

// Transposed feature scratch: [b][x][y][c] (channel-contiguous per texel)
__device__ float g_t1[BMAX * 56 * 56 * 64];
__device__ float g_t2[BMAX * 28 * 28 * 128];
__device__ float g_t3[BMAX * 14 * 14 * 256];
__device__ float g_t4[BMAX * 7  * 7  * 512];

// ---------------------------------------------------------------------------
// Fused transpose: all four [B,C,S,S] -> [B,S,S,C] in one launch.
// ---------------------------------------------------------------------------
__device__ __forceinline__ void tr_body(const float* __restrict__ in,
                                        float* __restrict__ out,
                                        int C, int S, int idx) {
    int c = idx % C;
    int y = (idx / C) % S;
    int x = (idx / (C * S)) % S;
    int b = idx / (C * S * S);
    out[idx] = in[((b * C + c) * S + x) * S + y];
}

__global__ __launch_bounds__(256)
void transpose_all(const float* __restrict__ f1, const float* __restrict__ f2,
                   const float* __restrict__ f3, const float* __restrict__ f4,
                   float* __restrict__ t1, float* __restrict__ t2,
                   float* __restrict__ t3, float* __restrict__ t4,
                   int n1, int n2, int n3, int n4) {
    int idx = blockIdx.x * blockDim.x + threadIdx.x;
    if (idx < n1)                     { tr_body(f1, t1, 64, 56, idx); return; }
    idx -= n1;
    if (idx < n2)                     { tr_body(f2, t2, 128, 28, idx); return; }
    idx -= n2;
    if (idx < n3)                     { tr_body(f3, t3, 256, 14, idx); return; }
    idx -= n3;
    if (idx < n4)                     { tr_body(f4, t4, 512, 7, idx); }
}

// ---------------------------------------------------------------------------
// Bilinear params for one level. Matches the reference exactly, including the
// all-zero-weight case when the clipped coord is an integer (floor==ceil).
// ---------------------------------------------------------------------------
__device__ __forceinline__ void level_params(float h, float w, float invsc,
                                             int S, int C, int base,
                                             float4* wout, int4* oout) {
    float x = fminf(h * invsc, (float)(S - 1));
    float y = fminf(w * invsc, (float)(S - 1));
    float x1f = floorf(x), x2f = ceilf(x);
    float y1f = floorf(y), y2f = ceilf(y);
    int x1 = (int)x1f, x2 = (int)x2f, y1 = (int)y1f, y2 = (int)y2f;
    float ax2 = x2f - x, ax1 = x - x1f;
    float ay2 = y2f - y, ay1 = y - y1f;
    *oout = make_int4(base + (x1 * S + y1) * C,    // Q11
                      base + (x2 * S + y1) * C,    // Q21
                      base + (x1 * S + y2) * C,    // Q12
                      base + (x2 * S + y2) * C);   // Q22
    *wout = make_float4(ax2 * ay2, ax1 * ay2, ax2 * ay1, ax1 * ay1);
}

// ---------------------------------------------------------------------------
// One level's gather body. Block = 256 threads = PT points x TPP2 threads.
// Each thread owns 4 float2 channel-pairs at 2q + j*(C/4):
//  - LDG.64 corner loads, lanes 8B apart -> dense 2-wavefront loads, half the
//    load instructions of the scalar version.
//  - scalar STG.32 (output rows are only 4B aligned), lane-consecutive dense.
// Params packed float4/int4; 2D grid (no divisions); streaming stores.
// ---------------------------------------------------------------------------
template<int TPP2, int PT, int LOG_TPP2, bool WRITE_COORD>
__device__ __forceinline__ void gather_body(int tile, int b,
                                            const float* __restrict__ coord,
                                            const float* __restrict__ t,
                                            float* __restrict__ out,
                                            int N, int S, float invsc, int ch_off) {
    __shared__ float4 sw[PT];
    __shared__ int4   so[PT];

    const int n0  = tile * PT;
    const int tid = threadIdx.x;
    constexpr int C   = TPP2 * 8;   // channels at this level
    constexpr int STR = C / 4;      // pair stride (even)

    if (tid < PT) {
        int n = n0 + tid;
        if (n < N) {
            float X = coord[3 * n + 0];
            float Y = coord[3 * n + 1];
            float Z = coord[3 * n + 2];
            float negZ = -Z;
            float h = fminf(fmaxf(250.0f * (-Y) / negZ + 112.0f, 0.0f), 223.0f);
            float w = fminf(fmaxf(250.0f * X / negZ + 112.0f, 0.0f), 223.0f);
            level_params(h, w, invsc, S, C, b * S * S * C, &sw[tid], &so[tid]);
            if (WRITE_COORD) {
                float* oc = out + ((unsigned)(b * N + n)) * 963u;
                __stcs(oc + 0, X);
                __stcs(oc + 1, Y);
                __stcs(oc + 2, Z);
            }
        }
    }
    __syncthreads();

    const int p  = tid >> LOG_TPP2;
    const int q2 = (tid & (TPP2 - 1)) * 2;   // even channel base
    const int n  = n0 + p;
    if (n >= N) return;

    const float4 w4 = sw[p];
    const int4   o4 = so[p];
    const float* __restrict__ b0 = t + o4.x + q2;
    const float* __restrict__ b1 = t + o4.y + q2;
    const float* __restrict__ b2 = t + o4.z + q2;
    const float* __restrict__ b3 = t + o4.w + q2;
    float* o = out + ((unsigned)(b * N + n) * 963u + (unsigned)(ch_off + q2));

    // 16 LDG.64 (all independent -> MLP=16), then combine, then store.
    float2 v0[4], v1[4], v2[4], v3[4];
    #pragma unroll
    for (int j = 0; j < 4; j++) {
        v0[j] = *(const float2*)(b0 + STR * j);
        v1[j] = *(const float2*)(b1 + STR * j);
        v2[j] = *(const float2*)(b2 + STR * j);
        v3[j] = *(const float2*)(b3 + STR * j);
    }
    #pragma unroll
    for (int j = 0; j < 4; j++) {
        __stcs(o + STR * j,
               w4.x * v0[j].x + w4.y * v1[j].x + w4.z * v2[j].x + w4.w * v3[j].x);
        __stcs(o + STR * j + 1,
               w4.x * v0[j].y + w4.y * v1[j].y + w4.z * v2[j].y + w4.w * v3[j].y);
    }
}

// ---------------------------------------------------------------------------
// Fused gather: blockIdx.y = batch; blockIdx.x partitioned by level (f4 first).
// e4/e3/e2 are cumulative per-batch block-range ends for levels 4,3,2.
// ---------------------------------------------------------------------------
__global__ __launch_bounds__(256)
void gather_all(const float* __restrict__ coord,
                const float* __restrict__ t1, const float* __restrict__ t2,
                const float* __restrict__ t3, const float* __restrict__ t4,
                float* __restrict__ out, int N,
                int e4, int e3, int e2) {
    const int bid = blockIdx.x;
    const int b   = blockIdx.y;
    if (bid < e4) {
        gather_body<64, 4, 6, false>(bid, b, coord, t4, out, N, 7, 0.03125f, 451);
    } else if (bid < e3) {
        gather_body<32, 8, 5, false>(bid - e4, b, coord, t3, out, N, 14, 0.0625f, 195);
    } else if (bid < e2) {
        gather_body<16, 16, 4, false>(bid - e3, b, coord, t2, out, N, 28, 0.125f, 67);
    } else {
        gather_body<8, 32, 3, true>(bid - e2, b, coord, t1, out, N, 56, 0.25f, 3);
    }
}

// ---------------------------------------------------------------------------
extern "C" void kernel_launch(void* const* d_in, const int* in_sizes, int n_in,
                              void* d_out, int out_size) {
    const float* inputs = (const float*)d_in[0];  // [B,N,3]; coord = inputs[0]
    const float* f1 = (const float*)d_in[1];
    const float* f2 = (const float*)d_in[2];
    const float* f3 = (const float*)d_in[3];
    const float* f4 = (const float*)d_in[4];
    float* out = (float*)d_out;

    const int B = in_sizes[1] / (64 * 56 * 56);
    const int N = in_sizes[0] / (3 * B);

    float* t1; float* t2; float* t3; float* t4;
    cudaGetSymbolAddress((void**)&t1, g_t1);
    cudaGetSymbolAddress((void**)&t2, g_t2);
    cudaGetSymbolAddress((void**)&t3, g_t3);
    cudaGetSymbolAddress((void**)&t4, g_t4);

    const int n1 = B * 64 * 56 * 56;
    const int n2 = B * 128 * 28 * 28;
    const int n3 = B * 256 * 14 * 14;
    const int n4 = B * 512 * 7 * 7;
    {
        int total = n1 + n2 + n3 + n4;
        transpose_all<<<(total + 255) / 256, 256>>>(f1, f2, f3, f4,
                                                    t1, t2, t3, t4,
                                                    n1, n2, n3, n4);
    }

    // Per-batch block counts per level (PT = 4, 8, 16, 32).
    const int nb4 = (N + 3) / 4;
    const int nb3 = (N + 7) / 8;
    const int nb2 = (N + 15) / 16;
    const int nb1 = (N + 31) / 32;
    const int e4 = nb4;
    const int e3 = e4 + nb3;
    const int e2 = e3 + nb2;
    const int xblocks = e2 + nb1;

    dim3 grid(xblocks, B);
    gather_all<<<grid, 256>>>(inputs, t1, t2, t3, t4, out, N, e4, e3, e2);
}